// round 5
// baseline (speedup 1.0000x reference)
#include <cuda_runtime.h>
#include <math.h>
#include <math_constants.h>

// Problem constants
#define Bq  2
#define Tq  1024
#define Dq  1024
#define Hq  16
#define FFq 4096
#define Lq  8
#define Vq  32000
#define HDq 64
#define Rq  (Bq * Tq)   // 2048 rows

// ---------------------------------------------------------------------------
// Scratch (device globals; no runtime allocation allowed)
// ---------------------------------------------------------------------------
__device__ float g_x  [Rq * Dq];       // residual stream
__device__ float g_ln [Rq * Dq];       // layernorm output
__device__ float g_qkv[Rq * 3 * Dq];   // q|k|v
__device__ float g_y  [Rq * Dq];       // attention output
__device__ float g_ff [Rq * FFq];      // mlp hidden

// ---------------------------------------------------------------------------
// Block reductions
// ---------------------------------------------------------------------------
__device__ __forceinline__ float block_sum(float v, float* sh) {
    int lane = threadIdx.x & 31, w = threadIdx.x >> 5, nw = blockDim.x >> 5;
    #pragma unroll
    for (int o = 16; o; o >>= 1) v += __shfl_xor_sync(0xffffffffu, v, o);
    if (lane == 0) sh[w] = v;
    __syncthreads();
    if (w == 0) {
        v = (lane < nw) ? sh[lane] : 0.0f;
        #pragma unroll
        for (int o = 16; o; o >>= 1) v += __shfl_xor_sync(0xffffffffu, v, o);
        if (lane == 0) sh[0] = v;
    }
    __syncthreads();
    float r = sh[0];
    __syncthreads();
    return r;
}

// ---------------------------------------------------------------------------
// Embedding + sinusoidal PE
// ---------------------------------------------------------------------------
__global__ void embed_kernel(const int* __restrict__ idx,
                             const float* __restrict__ emb,
                             float* __restrict__ x) {
    int row = blockIdx.x;           // 0..2047  (b*T + t)
    int t   = row % Tq;
    int tok = idx[row];
    const float* er = emb + (size_t)tok * Dq;
    const float neg_log = -logf(10000.0f) / (float)Dq;
    for (int d = threadIdx.x; d < Dq; d += blockDim.x) {
        int i2 = d & ~1;                     // even index 0,2,4,...
        float freq = expf(neg_log * (float)i2);
        float ang  = (float)t * freq;
        float pe   = (d & 1) ? cosf(ang) : sinf(ang);
        x[(size_t)row * Dq + d] = er[d] + pe;
    }
}

// ---------------------------------------------------------------------------
// LayerNorm (two-pass, 256 threads, 4 elems/thread, D=1024)
// ---------------------------------------------------------------------------
__global__ void ln_kernel(const float* __restrict__ x,
                          const float* __restrict__ sc,
                          const float* __restrict__ bi,
                          float* __restrict__ out) {
    __shared__ float sh[32];
    int row = blockIdx.x;
    const float* xr = x + (size_t)row * Dq;
    float v[4];
    float lsum = 0.0f;
    #pragma unroll
    for (int i = 0; i < 4; i++) {
        v[i] = xr[threadIdx.x + i * 256];
        lsum += v[i];
    }
    float mean = block_sum(lsum, sh) * (1.0f / (float)Dq);
    float lsq = 0.0f;
    #pragma unroll
    for (int i = 0; i < 4; i++) {
        float d = v[i] - mean;
        lsq += d * d;
    }
    float var = block_sum(lsq, sh) * (1.0f / (float)Dq);
    float inv = rsqrtf(var + 1e-5f);
    #pragma unroll
    for (int i = 0; i < 4; i++) {
        int d = threadIdx.x + i * 256;
        out[(size_t)row * Dq + d] = (v[i] - mean) * inv * sc[d] + bi[d];
    }
}

// ---------------------------------------------------------------------------
// TF32 tensor-core GEMM, double-buffered smem ping-pong.
//   EPI 0: C = AB + bias ; EPI 1: C += AB + bias ; EPI 2: C = gelu(AB + bias)
// 128x128 tile, BK=32, 256 threads (8 warps, 2x4), warp tile 64x32,
// mma.sync.m16n8k8 tf32, fp32 accumulate, XOR-swizzled smem.
// One __syncthreads per k-tile; LDG of tile t+1 overlaps compute of tile t.
// ---------------------------------------------------------------------------
__device__ __forceinline__ unsigned f2tf(float x) {
    unsigned r;
    asm("cvt.rna.tf32.f32 %0, %1;" : "=r"(r) : "f"(x));
    return r;
}

__device__ __forceinline__ void mma_tf32(float c[4],
                                         unsigned a0, unsigned a1, unsigned a2, unsigned a3,
                                         unsigned b0, unsigned b1) {
    asm volatile(
        "mma.sync.aligned.m16n8k8.row.col.f32.tf32.tf32.f32 "
        "{%0,%1,%2,%3}, {%4,%5,%6,%7}, {%8,%9}, {%0,%1,%2,%3};"
        : "+f"(c[0]), "+f"(c[1]), "+f"(c[2]), "+f"(c[3])
        : "r"(a0), "r"(a1), "r"(a2), "r"(a3), "r"(b0), "r"(b1));
}

template <int EPI>
__global__ __launch_bounds__(256)
void tgemm_kernel(const float* __restrict__ A, const float* __restrict__ B,
                  const float* __restrict__ bias, float* __restrict__ C,
                  int M, int N, int K) {
    constexpr int BM = 128, BN = 128, BK = 32;
    constexpr int ABUF = BK * BM;     // 4096 words
    constexpr int BBUF = BK * BN;     // 4096 words
    extern __shared__ unsigned smbuf[];
    unsigned* Asb = smbuf;                 // [2][BK][BM]  m ^ ((k&3)<<3)
    unsigned* Bsb = smbuf + 2 * ABUF;      // [2][BK][BN]  n ^ ((k&3)<<3)

    int tid  = threadIdx.x;
    int lane = tid & 31;
    int warp = tid >> 5;
    int g    = lane >> 2;       // group 0..7
    int tig  = lane & 3;        // thread-in-group 0..3
    int sw   = tig << 3;        // fragment XOR swizzle
    int wm   = warp & 1;        // warp M index
    int wn   = warp >> 1;       // warp N index
    int rm   = wm * 64;
    int cn   = wn * 32;

    const float* Ab = A + (size_t)(blockIdx.y * BM) * K;
    const float* Bb = B + (size_t)(blockIdx.x) * BN;

    float acc[4][4][4];
    #pragma unroll
    for (int mi = 0; mi < 4; mi++)
        #pragma unroll
        for (int ni = 0; ni < 4; ni++)
            #pragma unroll
            for (int c = 0; c < 4; c++) acc[mi][ni][c] = 0.0f;

    // per-thread gmem addressing (constant across tiles)
    int am[4], ak[4], bk[4], bc[4];
    #pragma unroll
    for (int i = 0; i < 4; i++) {
        int lin = tid + i * 256;
        am[i] = lin >> 3;
        ak[i] = (lin & 7) * 4;
        bk[i] = lin >> 5;
        bc[i] = (lin & 31) * 4;
    }

    float4 areg[4], breg[4];
    // prologue: load tile 0 and commit to buffer 0
    #pragma unroll
    for (int i = 0; i < 4; i++) {
        areg[i] = *(const float4*)(Ab + (size_t)am[i] * K + ak[i]);
        breg[i] = *(const float4*)(Bb + (size_t)bk[i] * N + bc[i]);
    }
    #pragma unroll
    for (int i = 0; i < 4; i++) {
        int m  = am[i], kq = ak[i];
        Asb[(kq + 0) * BM + (m ^ 0 )] = f2tf(areg[i].x);
        Asb[(kq + 1) * BM + (m ^ 8 )] = f2tf(areg[i].y);
        Asb[(kq + 2) * BM + (m ^ 16)] = f2tf(areg[i].z);
        Asb[(kq + 3) * BM + (m ^ 24)] = f2tf(areg[i].w);
        int kk = bk[i], c4 = bc[i];
        uint4 u;
        u.x = f2tf(breg[i].x); u.y = f2tf(breg[i].y);
        u.z = f2tf(breg[i].z); u.w = f2tf(breg[i].w);
        *(uint4*)&Bsb[kk * BN + (c4 ^ ((kk & 3) << 3))] = u;
    }
    __syncthreads();

    int ntiles = K / BK;
    for (int t = 0; t < ntiles; t++) {
        int p = t & 1;
        bool more = (t + 1 < ntiles);

        // issue LDG for next tile (latency hidden under this tile's compute)
        if (more) {
            int koff = (t + 1) * BK;
            #pragma unroll
            for (int i = 0; i < 4; i++) {
                areg[i] = *(const float4*)(Ab + (size_t)am[i] * K + koff + ak[i]);
                breg[i] = *(const float4*)(Bb + (size_t)(koff + bk[i]) * N + bc[i]);
            }
        }

        // compute on buffer p
        const unsigned* Asp = Asb + p * ABUF;
        const unsigned* Bsp = Bsb + p * BBUF;
        #pragma unroll
        for (int ks = 0; ks < 4; ks++) {
            int k0 = ks * 8;
            unsigned af[4][4], bf[4][2];
            #pragma unroll
            for (int mi = 0; mi < 4; mi++) {
                int m1 = rm + mi * 16 + g;
                int m2 = m1 + 8;
                af[mi][0] = Asp[(k0 + tig    ) * BM + (m1 ^ sw)];
                af[mi][1] = Asp[(k0 + tig    ) * BM + (m2 ^ sw)];
                af[mi][2] = Asp[(k0 + tig + 4) * BM + (m1 ^ sw)];
                af[mi][3] = Asp[(k0 + tig + 4) * BM + (m2 ^ sw)];
            }
            #pragma unroll
            for (int ni = 0; ni < 4; ni++) {
                int nb = cn + ni * 8 + g;
                bf[ni][0] = Bsp[(k0 + tig    ) * BN + (nb ^ sw)];
                bf[ni][1] = Bsp[(k0 + tig + 4) * BN + (nb ^ sw)];
            }
            #pragma unroll
            for (int mi = 0; mi < 4; mi++)
                #pragma unroll
                for (int ni = 0; ni < 4; ni++)
                    mma_tf32(acc[mi][ni],
                             af[mi][0], af[mi][1], af[mi][2], af[mi][3],
                             bf[ni][0], bf[ni][1]);
        }

        // commit next tile into the other buffer, one barrier per tile
        if (more) {
            unsigned* Asq = Asb + (p ^ 1) * ABUF;
            unsigned* Bsq = Bsb + (p ^ 1) * BBUF;
            #pragma unroll
            for (int i = 0; i < 4; i++) {
                int m  = am[i], kq = ak[i];
                Asq[(kq + 0) * BM + (m ^ 0 )] = f2tf(areg[i].x);
                Asq[(kq + 1) * BM + (m ^ 8 )] = f2tf(areg[i].y);
                Asq[(kq + 2) * BM + (m ^ 16)] = f2tf(areg[i].z);
                Asq[(kq + 3) * BM + (m ^ 24)] = f2tf(areg[i].w);
                int kk = bk[i], c4 = bc[i];
                uint4 u;
                u.x = f2tf(breg[i].x); u.y = f2tf(breg[i].y);
                u.z = f2tf(breg[i].z); u.w = f2tf(breg[i].w);
                *(uint4*)&Bsq[kk * BN + (c4 ^ ((kk & 3) << 3))] = u;
            }
            __syncthreads();
        }
    }

    // ---- epilogue ----
    #pragma unroll
    for (int ni = 0; ni < 4; ni++) {
        int gc = blockIdx.x * BN + cn + ni * 8 + 2 * tig;
        float bv0 = bias ? bias[gc]     : 0.0f;
        float bv1 = bias ? bias[gc + 1] : 0.0f;
        #pragma unroll
        for (int mi = 0; mi < 4; mi++) {
            int gr1 = blockIdx.y * BM + rm + mi * 16 + g;
            int gr2 = gr1 + 8;
            float v00 = acc[mi][ni][0] + bv0;
            float v01 = acc[mi][ni][1] + bv1;
            float v10 = acc[mi][ni][2] + bv0;
            float v11 = acc[mi][ni][3] + bv1;
            float* p1 = C + (size_t)gr1 * N + gc;
            float* p2 = C + (size_t)gr2 * N + gc;
            if (EPI == 0) {
                *(float2*)p1 = make_float2(v00, v01);
                *(float2*)p2 = make_float2(v10, v11);
            } else if (EPI == 1) {
                float2 o1 = *(const float2*)p1;
                float2 o2 = *(const float2*)p2;
                *(float2*)p1 = make_float2(o1.x + v00, o1.y + v01);
                *(float2*)p2 = make_float2(o2.x + v10, o2.y + v11);
            } else {
                const float inv_sqrt2 = 0.70710678118654752f;
                *(float2*)p1 = make_float2(
                    0.5f * v00 * (1.0f + erff(v00 * inv_sqrt2)),
                    0.5f * v01 * (1.0f + erff(v01 * inv_sqrt2)));
                *(float2*)p2 = make_float2(
                    0.5f * v10 * (1.0f + erff(v10 * inv_sqrt2)),
                    0.5f * v11 * (1.0f + erff(v11 * inv_sqrt2)));
            }
        }
    }
}

// ---------------------------------------------------------------------------
// Flash-style causal attention (unchanged from R3).
// ---------------------------------------------------------------------------
#define APAD 68

__global__ __launch_bounds__(256)
void attn2_kernel(const float* __restrict__ qkv, float* __restrict__ y) {
    extern __shared__ float sm[];
    float* Qs = sm;                   // [64][68]
    float* Ks = sm + 64 * APAD;       // [64][68]
    float* Vs = sm + 2 * 64 * APAD;   // [64][68]
    float* Ps = sm + 3 * 64 * APAD;   // [64][68]

    int qb = blockIdx.x, h = blockIdx.y, b = blockIdx.z;
    int tid = threadIdx.x;
    int lane = tid & 31, w = tid >> 5;

    const size_t rowstride = 3 * Dq;
    const float* qbase = qkv + ((size_t)(b * Tq + qb * 64)) * rowstride + h * HDq;

    #pragma unroll
    for (int i = 0; i < 4; i++) {
        int f = tid + i * 256;
        int r = f >> 4, c4 = (f & 15) * 4;
        float4 v = *(const float4*)(qbase + (size_t)r * rowstride + c4);
        float* dst = Qs + r * APAD + c4;
        dst[0] = v.x * 0.125f; dst[1] = v.y * 0.125f;
        dst[2] = v.z * 0.125f; dst[3] = v.w * 0.125f;
    }

    float out0[8], out1[8], mrow[8], lrow[8];
    #pragma unroll
    for (int r = 0; r < 8; r++) {
        out0[r] = 0.0f; out1[r] = 0.0f;
        mrow[r] = -CUDART_INF_F; lrow[r] = 0.0f;
    }

    for (int kt = 0; kt <= qb; kt++) {
        __syncthreads();
        const float* kbase = qkv + ((size_t)(b * Tq + kt * 64)) * rowstride + Dq + h * HDq;
        const float* vbase = kbase + Dq;
        #pragma unroll
        for (int i = 0; i < 4; i++) {
            int f = tid + i * 256;
            int r = f >> 4, c4 = (f & 15) * 4;
            *(float4*)(Ks + r * APAD + c4) = *(const float4*)(kbase + (size_t)r * rowstride + c4);
            *(float4*)(Vs + r * APAD + c4) = *(const float4*)(vbase + (size_t)r * rowstride + c4);
        }
        __syncthreads();

        float s0[8], s1[8];
        #pragma unroll
        for (int r = 0; r < 8; r++) { s0[r] = 0.0f; s1[r] = 0.0f; }
        const float4* K0 = (const float4*)(Ks + lane * APAD);
        const float4* K1 = (const float4*)(Ks + (lane + 32) * APAD);
        #pragma unroll
        for (int j = 0; j < 16; j++) {
            float4 k0 = K0[j], k1 = K1[j];
            #pragma unroll
            for (int r = 0; r < 8; r++) {
                float4 qv = *(const float4*)(Qs + (w * 8 + r) * APAD + j * 4);
                s0[r] += qv.x * k0.x + qv.y * k0.y + qv.z * k0.z + qv.w * k0.w;
                s1[r] += qv.x * k1.x + qv.y * k1.y + qv.z * k1.z + qv.w * k1.w;
            }
        }

        bool diag = (kt == qb);
        #pragma unroll
        for (int r = 0; r < 8; r++) {
            int rloc = w * 8 + r;
            float a0 = s0[r], a1 = s1[r];
            if (diag) {
                if (lane      > rloc) a0 = -CUDART_INF_F;
                if (lane + 32 > rloc) a1 = -CUDART_INF_F;
            }
            float mx = fmaxf(a0, a1);
            #pragma unroll
            for (int o = 16; o; o >>= 1) mx = fmaxf(mx, __shfl_xor_sync(0xffffffffu, mx, o));
            float mnew = fmaxf(mrow[r], mx);
            float corr = __expf(mrow[r] - mnew);
            float p0 = __expf(a0 - mnew);
            float p1 = __expf(a1 - mnew);
            float ps = p0 + p1;
            #pragma unroll
            for (int o = 16; o; o >>= 1) ps += __shfl_xor_sync(0xffffffffu, ps, o);
            lrow[r] = lrow[r] * corr + ps;
            out0[r] *= corr; out1[r] *= corr;
            mrow[r] = mnew;
            Ps[(w * 8 + r) * APAD + lane]      = p0;
            Ps[(w * 8 + r) * APAD + lane + 32] = p1;
        }
        __syncwarp();

        #pragma unroll
        for (int c4 = 0; c4 < 16; c4++) {
            float v0[4], v1[4];
            #pragma unroll
            for (int i = 0; i < 4; i++) {
                v0[i] = Vs[(c4 * 4 + i) * APAD + lane];
                v1[i] = Vs[(c4 * 4 + i) * APAD + lane + 32];
            }
            #pragma unroll
            for (int r = 0; r < 8; r++) {
                float4 p = *(const float4*)(Ps + (w * 8 + r) * APAD + c4 * 4);
                out0[r] += p.x * v0[0] + p.y * v0[1] + p.z * v0[2] + p.w * v0[3];
                out1[r] += p.x * v1[0] + p.y * v1[1] + p.z * v1[2] + p.w * v1[3];
            }
        }
        __syncwarp();
    }

    #pragma unroll
    for (int r = 0; r < 8; r++) {
        float inv = 1.0f / lrow[r];
        size_t row = (size_t)(b * Tq + qb * 64 + w * 8 + r);
        float* yr = y + row * Dq + h * HDq;
        yr[lane]      = out0[r] * inv;
        yr[lane + 32] = out1[r] * inv;
    }
}

// ---------------------------------------------------------------------------
// Launch
// ---------------------------------------------------------------------------
extern "C" void kernel_launch(void* const* d_in, const int* in_sizes, int n_in,
                              void* d_out, int out_size) {
    const int*   idx     = (const int*)  d_in[0];
    const float* tok_emb = (const float*)d_in[1];
    const float* ln1_s   = (const float*)d_in[2];
    const float* ln1_b   = (const float*)d_in[3];
    const float* qkv_w   = (const float*)d_in[4];
    const float* qkv_b   = (const float*)d_in[5];
    const float* out_w   = (const float*)d_in[6];
    const float* out_b   = (const float*)d_in[7];
    const float* ln2_s   = (const float*)d_in[8];
    const float* ln2_b   = (const float*)d_in[9];
    const float* mlp_w1  = (const float*)d_in[10];
    const float* mlp_b1  = (const float*)d_in[11];
    const float* mlp_w2  = (const float*)d_in[12];
    const float* mlp_b2  = (const float*)d_in[13];
    const float* lnf_s   = (const float*)d_in[14];
    const float* lnf_b   = (const float*)d_in[15];
    const float* head_w  = (const float*)d_in[16];
    float* logits = (float*)d_out;

    float *x, *ln, *qkv, *y, *ff;
    cudaGetSymbolAddress((void**)&x,   g_x);
    cudaGetSymbolAddress((void**)&ln,  g_ln);
    cudaGetSymbolAddress((void**)&qkv, g_qkv);
    cudaGetSymbolAddress((void**)&y,   g_y);
    cudaGetSymbolAddress((void**)&ff,  g_ff);

    const int gemm_smem = 2 * (32 * 128 + 32 * 128) * (int)sizeof(unsigned);  // 64 KB
    cudaFuncSetAttribute(tgemm_kernel<0>,
                         cudaFuncAttributeMaxDynamicSharedMemorySize, gemm_smem);
    cudaFuncSetAttribute(tgemm_kernel<1>,
                         cudaFuncAttributeMaxDynamicSharedMemorySize, gemm_smem);
    cudaFuncSetAttribute(tgemm_kernel<2>,
                         cudaFuncAttributeMaxDynamicSharedMemorySize, gemm_smem);
    const int attn_smem = 4 * 64 * APAD * (int)sizeof(float);  // ~69.6 KB
    cudaFuncSetAttribute(attn2_kernel,
                         cudaFuncAttributeMaxDynamicSharedMemorySize, attn_smem);

    embed_kernel<<<Rq, 256>>>(idx, tok_emb, x);

    for (int l = 0; l < Lq; l++) {
        ln_kernel<<<Rq, 256>>>(x, ln1_s + (size_t)l * Dq, ln1_b + (size_t)l * Dq, ln);
        tgemm_kernel<0><<<dim3(3 * Dq / 128, Rq / 128), 256, gemm_smem>>>(
            ln, qkv_w + (size_t)l * Dq * 3 * Dq, qkv_b + (size_t)l * 3 * Dq,
            qkv, Rq, 3 * Dq, Dq);
        attn2_kernel<<<dim3(Tq / 64, Hq, Bq), 256, attn_smem>>>(qkv, y);
        tgemm_kernel<1><<<dim3(Dq / 128, Rq / 128), 256, gemm_smem>>>(
            y, out_w + (size_t)l * Dq * Dq, out_b + (size_t)l * Dq,
            x, Rq, Dq, Dq);
        ln_kernel<<<Rq, 256>>>(x, ln2_s + (size_t)l * Dq, ln2_b + (size_t)l * Dq, ln);
        tgemm_kernel<2><<<dim3(FFq / 128, Rq / 128), 256, gemm_smem>>>(
            ln, mlp_w1 + (size_t)l * Dq * FFq, mlp_b1 + (size_t)l * FFq,
            ff, Rq, FFq, Dq);
        tgemm_kernel<1><<<dim3(Dq / 128, Rq / 128), 256, gemm_smem>>>(
            ff, mlp_w2 + (size_t)l * FFq * Dq, mlp_b2 + (size_t)l * Dq,
            x, Rq, Dq, FFq);
    }

    ln_kernel<<<Rq, 256>>>(x, lnf_s, lnf_b, ln);
    tgemm_kernel<0><<<dim3(Vq / 128, Rq / 128), 256, gemm_smem>>>(
        ln, head_w, (const float*)nullptr, logits, Rq, Vq, Dq);
}

// round 6
// speedup vs baseline: 1.4943x; 1.4943x over previous
#include <cuda_runtime.h>
#include <math.h>
#include <math_constants.h>

// Problem constants
#define Bq  2
#define Tq  1024
#define Dq  1024
#define Hq  16
#define FFq 4096
#define Lq  8
#define Vq  32000
#define HDq 64
#define Rq  (Bq * Tq)   // 2048 rows

// ---------------------------------------------------------------------------
// Scratch (device globals; no runtime allocation allowed)
// ---------------------------------------------------------------------------
__device__ float g_x  [Rq * Dq];       // residual stream
__device__ float g_ln [Rq * Dq];       // layernorm output (tf32-rounded)
__device__ float g_qkv[Rq * 3 * Dq];   // q|k|v
__device__ float g_y  [Rq * Dq];       // attention output (tf32-rounded)
__device__ float g_ff [Rq * FFq];      // mlp hidden (tf32-rounded)

// tf32-rounded weight copies (rounded once per launch)
__device__ float g_wqkv[Lq * Dq * 3 * Dq];   // 25.2M
__device__ float g_wout[Lq * Dq * Dq];       //  8.4M
__device__ float g_wm1 [Lq * Dq * FFq];      // 33.6M
__device__ float g_wm2 [Lq * FFq * Dq];      // 33.6M
__device__ float g_whd [Dq * Vq];            // 32.8M

// ---------------------------------------------------------------------------
__device__ __forceinline__ unsigned f2tf(float x) {
    unsigned r;
    asm("cvt.rna.tf32.f32 %0, %1;" : "=r"(r) : "f"(x));
    return r;
}
__device__ __forceinline__ float round_tf(float x) {
    return __uint_as_float(f2tf(x));
}

__global__ void round_kernel(const float* __restrict__ in,
                             float* __restrict__ out, int n) {
    for (int i = blockIdx.x * blockDim.x + threadIdx.x; i < n;
         i += gridDim.x * blockDim.x)
        out[i] = round_tf(in[i]);
}

// ---------------------------------------------------------------------------
// Block reductions
// ---------------------------------------------------------------------------
__device__ __forceinline__ float block_sum(float v, float* sh) {
    int lane = threadIdx.x & 31, w = threadIdx.x >> 5, nw = blockDim.x >> 5;
    #pragma unroll
    for (int o = 16; o; o >>= 1) v += __shfl_xor_sync(0xffffffffu, v, o);
    if (lane == 0) sh[w] = v;
    __syncthreads();
    if (w == 0) {
        v = (lane < nw) ? sh[lane] : 0.0f;
        #pragma unroll
        for (int o = 16; o; o >>= 1) v += __shfl_xor_sync(0xffffffffu, v, o);
        if (lane == 0) sh[0] = v;
    }
    __syncthreads();
    float r = sh[0];
    __syncthreads();
    return r;
}

// ---------------------------------------------------------------------------
// Embedding + sinusoidal PE
// ---------------------------------------------------------------------------
__global__ void embed_kernel(const int* __restrict__ idx,
                             const float* __restrict__ emb,
                             float* __restrict__ x) {
    int row = blockIdx.x;
    int t   = row % Tq;
    int tok = idx[row];
    const float* er = emb + (size_t)tok * Dq;
    const float neg_log = -logf(10000.0f) / (float)Dq;
    for (int d = threadIdx.x; d < Dq; d += blockDim.x) {
        int i2 = d & ~1;
        float freq = expf(neg_log * (float)i2);
        float ang  = (float)t * freq;
        float pe   = (d & 1) ? cosf(ang) : sinf(ang);
        x[(size_t)row * Dq + d] = er[d] + pe;
    }
}

// ---------------------------------------------------------------------------
// LayerNorm; output rounded to tf32 (feeds GEMM A only)
// ---------------------------------------------------------------------------
__global__ void ln_kernel(const float* __restrict__ x,
                          const float* __restrict__ sc,
                          const float* __restrict__ bi,
                          float* __restrict__ out) {
    __shared__ float sh[32];
    int row = blockIdx.x;
    const float* xr = x + (size_t)row * Dq;
    float v[4];
    float lsum = 0.0f;
    #pragma unroll
    for (int i = 0; i < 4; i++) {
        v[i] = xr[threadIdx.x + i * 256];
        lsum += v[i];
    }
    float mean = block_sum(lsum, sh) * (1.0f / (float)Dq);
    float lsq = 0.0f;
    #pragma unroll
    for (int i = 0; i < 4; i++) {
        float d = v[i] - mean;
        lsq += d * d;
    }
    float var = block_sum(lsq, sh) * (1.0f / (float)Dq);
    float inv = rsqrtf(var + 1e-5f);
    #pragma unroll
    for (int i = 0; i < 4; i++) {
        int d = threadIdx.x + i * 256;
        out[(size_t)row * Dq + d] = round_tf((v[i] - mean) * inv * sc[d] + bi[d]);
    }
}

// ---------------------------------------------------------------------------
// TF32 tensor-core GEMM, cp.async double-buffer, 4 warps, warp tile 64x64.
//   EPI 0: C = AB + bias ; EPI 1: C += AB + bias ; EPI 2: C = gelu(AB+bias) [tf32-rounded]
// CTA tile 128x128, BK=32, 128 threads (2x2 warps).
// A smem [128][32] row-swizzled (k ^ 4*(m&7)); B smem [32][128] (n ^ 8*(k&3)).
// Inputs assumed already tf32-rounded (producers round; weights pre-rounded).
// ---------------------------------------------------------------------------
__device__ __forceinline__ void mma_tf32(float c[4],
                                         unsigned a0, unsigned a1, unsigned a2, unsigned a3,
                                         unsigned b0, unsigned b1) {
    asm volatile(
        "mma.sync.aligned.m16n8k8.row.col.f32.tf32.tf32.f32 "
        "{%0,%1,%2,%3}, {%4,%5,%6,%7}, {%8,%9}, {%0,%1,%2,%3};"
        : "+f"(c[0]), "+f"(c[1]), "+f"(c[2]), "+f"(c[3])
        : "r"(a0), "r"(a1), "r"(a2), "r"(a3), "r"(b0), "r"(b1));
}

#define CP16(dst, src) \
    asm volatile("cp.async.cg.shared.global [%0], [%1], 16;\n" :: "r"(dst), "l"(src))

template <int EPI>
__global__ __launch_bounds__(128)
void tgemm_kernel(const float* __restrict__ A, const float* __restrict__ B,
                  const float* __restrict__ bias, float* __restrict__ C,
                  int M, int N, int K) {
    constexpr int BM = 128, BN = 128, BK = 32;
    constexpr int ASZ = BM * BK;   // 4096 floats
    constexpr int BSZ = BK * BN;   // 4096 floats
    extern __shared__ float smf[];
    float* Abuf = smf;             // [2][128][32]
    float* Bbuf = smf + 2 * ASZ;   // [2][32][128]

    int tid  = threadIdx.x;
    int lane = tid & 31;
    int warp = tid >> 5;
    int g    = lane >> 2;       // 0..7
    int tig  = lane & 3;        // 0..3
    int wm   = warp & 1;
    int wn   = warp >> 1;
    int rm   = wm * 64;
    int cn   = wn * 64;
    unsigned xora = (unsigned)(g << 2);     // A fragment swizzle
    unsigned xorb = (unsigned)(tig << 3);   // B fragment swizzle

    const float* Ab = A + (size_t)(blockIdx.y * BM) * K;
    const float* Bb = B + (size_t)(blockIdx.x) * BN;

    float acc[4][8][4];
    #pragma unroll
    for (int mi = 0; mi < 4; mi++)
        #pragma unroll
        for (int ni = 0; ni < 8; ni++)
            #pragma unroll
            for (int c = 0; c < 4; c++) acc[mi][ni][c] = 0.0f;

    // copy-thread mapping (constant per thread)
    int a_m   = tid >> 3;              // + i*16
    int a_k4  = (tid & 7) << 2;
    int b_k   = tid >> 5;              // + i*4
    int b_n4  = (tid & 31) << 2;
    unsigned xsta = (unsigned)((a_m & 7) << 2);   // A store swizzle (m&7 const)
    unsigned xstb = (unsigned)((b_k & 3) << 3);   // B store swizzle (k&3 const)

    unsigned sA0 = (unsigned)__cvta_generic_to_shared(Abuf);
    unsigned sB0 = (unsigned)__cvta_generic_to_shared(Bbuf);

    auto issue = [&](int kt, int p) {
        unsigned sa = sA0 + (unsigned)(p * ASZ) * 4u;
        unsigned sb = sB0 + (unsigned)(p * BSZ) * 4u;
        #pragma unroll
        for (int i = 0; i < 8; i++) {
            int m = i * 16 + a_m;
            const float* src = Ab + (size_t)m * K + kt + a_k4;
            unsigned dst = sa + (unsigned)(m * 32 + ((unsigned)a_k4 ^ xsta)) * 4u;
            CP16(dst, src);
        }
        #pragma unroll
        for (int i = 0; i < 8; i++) {
            int k = i * 4 + b_k;
            const float* src = Bb + (size_t)(kt + k) * N + b_n4;
            unsigned dst = sb + (unsigned)(k * 128 + ((unsigned)b_n4 ^ xstb)) * 4u;
            CP16(dst, src);
        }
        asm volatile("cp.async.commit_group;\n");
    };

    issue(0, 0);

    int ntiles = K / BK;
    for (int t = 0; t < ntiles; t++) {
        int p = t & 1;
        asm volatile("cp.async.wait_group 0;\n");
        __syncthreads();
        if (t + 1 < ntiles) issue((t + 1) * BK, p ^ 1);

        const float* Ap = Abuf + p * ASZ;
        const float* Bp = Bbuf + p * BSZ;
        #pragma unroll
        for (int ks = 0; ks < 4; ks++) {
            int k0 = ks * 8;
            unsigned af[4][4], bf[8][2];
            unsigned ka0 = (unsigned)(k0 + tig)     ^ xora;
            unsigned ka1 = (unsigned)(k0 + tig + 4) ^ xora;
            #pragma unroll
            for (int mi = 0; mi < 4; mi++) {
                int m1 = rm + mi * 16 + g;
                int m2 = m1 + 8;
                af[mi][0] = __float_as_uint(Ap[m1 * 32 + ka0]);
                af[mi][1] = __float_as_uint(Ap[m2 * 32 + ka0]);
                af[mi][2] = __float_as_uint(Ap[m1 * 32 + ka1]);
                af[mi][3] = __float_as_uint(Ap[m2 * 32 + ka1]);
            }
            #pragma unroll
            for (int ni = 0; ni < 8; ni++) {
                unsigned nb = (unsigned)(cn + ni * 8 + g) ^ xorb;
                bf[ni][0] = __float_as_uint(Bp[(k0 + tig)     * 128 + nb]);
                bf[ni][1] = __float_as_uint(Bp[(k0 + tig + 4) * 128 + nb]);
            }
            #pragma unroll
            for (int mi = 0; mi < 4; mi++)
                #pragma unroll
                for (int ni = 0; ni < 8; ni++)
                    mma_tf32(acc[mi][ni],
                             af[mi][0], af[mi][1], af[mi][2], af[mi][3],
                             bf[ni][0], bf[ni][1]);
        }
        __syncthreads();
    }

    // ---- epilogue ----
    #pragma unroll
    for (int ni = 0; ni < 8; ni++) {
        int gc = blockIdx.x * BN + cn + ni * 8 + 2 * tig;
        float bv0 = bias ? bias[gc]     : 0.0f;
        float bv1 = bias ? bias[gc + 1] : 0.0f;
        #pragma unroll
        for (int mi = 0; mi < 4; mi++) {
            int gr1 = blockIdx.y * BM + rm + mi * 16 + g;
            int gr2 = gr1 + 8;
            float v00 = acc[mi][ni][0] + bv0;
            float v01 = acc[mi][ni][1] + bv1;
            float v10 = acc[mi][ni][2] + bv0;
            float v11 = acc[mi][ni][3] + bv1;
            float* p1 = C + (size_t)gr1 * N + gc;
            float* p2 = C + (size_t)gr2 * N + gc;
            if (EPI == 0) {
                *(float2*)p1 = make_float2(v00, v01);
                *(float2*)p2 = make_float2(v10, v11);
            } else if (EPI == 1) {
                float2 o1 = *(const float2*)p1;
                float2 o2 = *(const float2*)p2;
                *(float2*)p1 = make_float2(o1.x + v00, o1.y + v01);
                *(float2*)p2 = make_float2(o2.x + v10, o2.y + v11);
            } else {
                const float is2 = 0.70710678118654752f;
                *(float2*)p1 = make_float2(
                    round_tf(0.5f * v00 * (1.0f + erff(v00 * is2))),
                    round_tf(0.5f * v01 * (1.0f + erff(v01 * is2))));
                *(float2*)p2 = make_float2(
                    round_tf(0.5f * v10 * (1.0f + erff(v10 * is2))),
                    round_tf(0.5f * v11 * (1.0f + erff(v11 * is2))));
            }
        }
    }
}

// ---------------------------------------------------------------------------
// Flash-style causal attention (proven R3 version; y rounded to tf32).
// ---------------------------------------------------------------------------
#define APAD 68

__global__ __launch_bounds__(256)
void attn2_kernel(const float* __restrict__ qkv, float* __restrict__ y) {
    extern __shared__ float sm[];
    float* Qs = sm;
    float* Ks = sm + 64 * APAD;
    float* Vs = sm + 2 * 64 * APAD;
    float* Ps = sm + 3 * 64 * APAD;

    int qb = blockIdx.x, h = blockIdx.y, b = blockIdx.z;
    int tid = threadIdx.x;
    int lane = tid & 31, w = tid >> 5;

    const size_t rowstride = 3 * Dq;
    const float* qbase = qkv + ((size_t)(b * Tq + qb * 64)) * rowstride + h * HDq;

    #pragma unroll
    for (int i = 0; i < 4; i++) {
        int f = tid + i * 256;
        int r = f >> 4, c4 = (f & 15) * 4;
        float4 v = *(const float4*)(qbase + (size_t)r * rowstride + c4);
        float* dst = Qs + r * APAD + c4;
        dst[0] = v.x * 0.125f; dst[1] = v.y * 0.125f;
        dst[2] = v.z * 0.125f; dst[3] = v.w * 0.125f;
    }

    float out0[8], out1[8], mrow[8], lrow[8];
    #pragma unroll
    for (int r = 0; r < 8; r++) {
        out0[r] = 0.0f; out1[r] = 0.0f;
        mrow[r] = -CUDART_INF_F; lrow[r] = 0.0f;
    }

    for (int kt = 0; kt <= qb; kt++) {
        __syncthreads();
        const float* kbase = qkv + ((size_t)(b * Tq + kt * 64)) * rowstride + Dq + h * HDq;
        const float* vbase = kbase + Dq;
        #pragma unroll
        for (int i = 0; i < 4; i++) {
            int f = tid + i * 256;
            int r = f >> 4, c4 = (f & 15) * 4;
            *(float4*)(Ks + r * APAD + c4) = *(const float4*)(kbase + (size_t)r * rowstride + c4);
            *(float4*)(Vs + r * APAD + c4) = *(const float4*)(vbase + (size_t)r * rowstride + c4);
        }
        __syncthreads();

        float s0[8], s1[8];
        #pragma unroll
        for (int r = 0; r < 8; r++) { s0[r] = 0.0f; s1[r] = 0.0f; }
        const float4* K0 = (const float4*)(Ks + lane * APAD);
        const float4* K1 = (const float4*)(Ks + (lane + 32) * APAD);
        #pragma unroll
        for (int j = 0; j < 16; j++) {
            float4 k0 = K0[j], k1 = K1[j];
            #pragma unroll
            for (int r = 0; r < 8; r++) {
                float4 qv = *(const float4*)(Qs + (w * 8 + r) * APAD + j * 4);
                s0[r] += qv.x * k0.x + qv.y * k0.y + qv.z * k0.z + qv.w * k0.w;
                s1[r] += qv.x * k1.x + qv.y * k1.y + qv.z * k1.z + qv.w * k1.w;
            }
        }

        bool diag = (kt == qb);
        #pragma unroll
        for (int r = 0; r < 8; r++) {
            int rloc = w * 8 + r;
            float a0 = s0[r], a1 = s1[r];
            if (diag) {
                if (lane      > rloc) a0 = -CUDART_INF_F;
                if (lane + 32 > rloc) a1 = -CUDART_INF_F;
            }
            float mx = fmaxf(a0, a1);
            #pragma unroll
            for (int o = 16; o; o >>= 1) mx = fmaxf(mx, __shfl_xor_sync(0xffffffffu, mx, o));
            float mnew = fmaxf(mrow[r], mx);
            float corr = __expf(mrow[r] - mnew);
            float p0 = __expf(a0 - mnew);
            float p1 = __expf(a1 - mnew);
            float ps = p0 + p1;
            #pragma unroll
            for (int o = 16; o; o >>= 1) ps += __shfl_xor_sync(0xffffffffu, ps, o);
            lrow[r] = lrow[r] * corr + ps;
            out0[r] *= corr; out1[r] *= corr;
            mrow[r] = mnew;
            Ps[(w * 8 + r) * APAD + lane]      = p0;
            Ps[(w * 8 + r) * APAD + lane + 32] = p1;
        }
        __syncwarp();

        #pragma unroll
        for (int c4 = 0; c4 < 16; c4++) {
            float v0[4], v1[4];
            #pragma unroll
            for (int i = 0; i < 4; i++) {
                v0[i] = Vs[(c4 * 4 + i) * APAD + lane];
                v1[i] = Vs[(c4 * 4 + i) * APAD + lane + 32];
            }
            #pragma unroll
            for (int r = 0; r < 8; r++) {
                float4 p = *(const float4*)(Ps + (w * 8 + r) * APAD + c4 * 4);
                out0[r] += p.x * v0[0] + p.y * v0[1] + p.z * v0[2] + p.w * v0[3];
                out1[r] += p.x * v1[0] + p.y * v1[1] + p.z * v1[2] + p.w * v1[3];
            }
        }
        __syncwarp();
    }

    #pragma unroll
    for (int r = 0; r < 8; r++) {
        float inv = 1.0f / lrow[r];
        size_t row = (size_t)(b * Tq + qb * 64 + w * 8 + r);
        float* yr = y + row * Dq + h * HDq;
        yr[lane]      = round_tf(out0[r] * inv);
        yr[lane + 32] = round_tf(out1[r] * inv);
    }
}

// ---------------------------------------------------------------------------
// Launch
// ---------------------------------------------------------------------------
extern "C" void kernel_launch(void* const* d_in, const int* in_sizes, int n_in,
                              void* d_out, int out_size) {
    const int*   idx     = (const int*)  d_in[0];
    const float* tok_emb = (const float*)d_in[1];
    const float* ln1_s   = (const float*)d_in[2];
    const float* ln1_b   = (const float*)d_in[3];
    const float* qkv_w   = (const float*)d_in[4];
    const float* qkv_b   = (const float*)d_in[5];
    const float* out_w   = (const float*)d_in[6];
    const float* out_b   = (const float*)d_in[7];
    const float* ln2_s   = (const float*)d_in[8];
    const float* ln2_b   = (const float*)d_in[9];
    const float* mlp_w1  = (const float*)d_in[10];
    const float* mlp_b1  = (const float*)d_in[11];
    const float* mlp_w2  = (const float*)d_in[12];
    const float* mlp_b2  = (const float*)d_in[13];
    const float* lnf_s   = (const float*)d_in[14];
    const float* lnf_b   = (const float*)d_in[15];
    const float* head_w  = (const float*)d_in[16];
    float* logits = (float*)d_out;

    float *x, *ln, *qkv, *y, *ff;
    float *wqkv, *wout, *wm1, *wm2, *whd;
    cudaGetSymbolAddress((void**)&x,    g_x);
    cudaGetSymbolAddress((void**)&ln,   g_ln);
    cudaGetSymbolAddress((void**)&qkv,  g_qkv);
    cudaGetSymbolAddress((void**)&y,    g_y);
    cudaGetSymbolAddress((void**)&ff,   g_ff);
    cudaGetSymbolAddress((void**)&wqkv, g_wqkv);
    cudaGetSymbolAddress((void**)&wout, g_wout);
    cudaGetSymbolAddress((void**)&wm1,  g_wm1);
    cudaGetSymbolAddress((void**)&wm2,  g_wm2);
    cudaGetSymbolAddress((void**)&whd,  g_whd);

    const int gemm_smem = 2 * (128 * 32 + 32 * 128) * (int)sizeof(float);  // 64 KB
    cudaFuncSetAttribute(tgemm_kernel<0>,
                         cudaFuncAttributeMaxDynamicSharedMemorySize, gemm_smem);
    cudaFuncSetAttribute(tgemm_kernel<1>,
                         cudaFuncAttributeMaxDynamicSharedMemorySize, gemm_smem);
    cudaFuncSetAttribute(tgemm_kernel<2>,
                         cudaFuncAttributeMaxDynamicSharedMemorySize, gemm_smem);
    const int attn_smem = 4 * 64 * APAD * (int)sizeof(float);
    cudaFuncSetAttribute(attn2_kernel,
                         cudaFuncAttributeMaxDynamicSharedMemorySize, attn_smem);

    // round weights to tf32 once (graph-capturable, deterministic)
    round_kernel<<<4096, 256>>>(qkv_w,  wqkv, Lq * Dq * 3 * Dq);
    round_kernel<<<4096, 256>>>(out_w,  wout, Lq * Dq * Dq);
    round_kernel<<<4096, 256>>>(mlp_w1, wm1,  Lq * Dq * FFq);
    round_kernel<<<4096, 256>>>(mlp_w2, wm2,  Lq * FFq * Dq);
    round_kernel<<<4096, 256>>>(head_w, whd,  Dq * Vq);

    embed_kernel<<<Rq, 256>>>(idx, tok_emb, x);

    for (int l = 0; l < Lq; l++) {
        ln_kernel<<<Rq, 256>>>(x, ln1_s + (size_t)l * Dq, ln1_b + (size_t)l * Dq, ln);
        tgemm_kernel<0><<<dim3(3 * Dq / 128, Rq / 128), 128, gemm_smem>>>(
            ln, wqkv + (size_t)l * Dq * 3 * Dq, qkv_b + (size_t)l * 3 * Dq,
            qkv, Rq, 3 * Dq, Dq);
        attn2_kernel<<<dim3(Tq / 64, Hq, Bq), 256, attn_smem>>>(qkv, y);
        tgemm_kernel<1><<<dim3(Dq / 128, Rq / 128), 128, gemm_smem>>>(
            y, wout + (size_t)l * Dq * Dq, out_b + (size_t)l * Dq,
            x, Rq, Dq, Dq);
        ln_kernel<<<Rq, 256>>>(x, ln2_s + (size_t)l * Dq, ln2_b + (size_t)l * Dq, ln);
        tgemm_kernel<2><<<dim3(FFq / 128, Rq / 128), 128, gemm_smem>>>(
            ln, wm1 + (size_t)l * Dq * FFq, mlp_b1 + (size_t)l * FFq,
            ff, Rq, FFq, Dq);
        tgemm_kernel<1><<<dim3(Dq / 128, Rq / 128), 128, gemm_smem>>>(
            ff, wm2 + (size_t)l * FFq * Dq, mlp_b2 + (size_t)l * Dq,
            x, Rq, Dq, FFq);
    }

    ln_kernel<<<Rq, 256>>>(x, lnf_s, lnf_b, ln);
    tgemm_kernel<0><<<dim3(Vq / 128, Rq / 128), 128, gemm_smem>>>(
        ln, whd, (const float*)nullptr, logits, Rq, Vq, Dq);
}

// round 7
// speedup vs baseline: 1.9691x; 1.3177x over previous
#include <cuda_runtime.h>
#include <math.h>
#include <math_constants.h>

// Problem constants
#define Bq  2
#define Tq  1024
#define Dq  1024
#define Hq  16
#define FFq 4096
#define Lq  8
#define Vq  32000
#define HDq 64
#define Rq  (Bq * Tq)   // 2048 rows

// ---------------------------------------------------------------------------
// Scratch (device globals; no runtime allocation allowed)
// ---------------------------------------------------------------------------
__device__ float g_x  [Rq * Dq];       // residual stream
__device__ float g_ln [Rq * Dq];       // layernorm output (tf32-rounded)
__device__ float g_qkv[Rq * 3 * Dq];   // q|k|v
__device__ float g_y  [Rq * Dq];       // attention output (tf32-rounded)
__device__ float g_ff [Rq * FFq];      // mlp hidden (tf32-rounded)

// tf32-rounded weight copies (rounded once per launch)
__device__ float g_wqkv[Lq * Dq * 3 * Dq];
__device__ float g_wout[Lq * Dq * Dq];
__device__ float g_wm1 [Lq * Dq * FFq];
__device__ float g_wm2 [Lq * FFq * Dq];
__device__ float g_whd [Dq * Vq];

// ---------------------------------------------------------------------------
__device__ __forceinline__ unsigned f2tf(float x) {
    unsigned r;
    asm("cvt.rna.tf32.f32 %0, %1;" : "=r"(r) : "f"(x));
    return r;
}
__device__ __forceinline__ float round_tf(float x) {
    return __uint_as_float(f2tf(x));
}

__global__ void round4_kernel(const float4* __restrict__ in,
                              float4* __restrict__ out, int n4) {
    int i = blockIdx.x * blockDim.x + threadIdx.x;
    if (i < n4) {
        float4 v = in[i];
        out[i] = make_float4(round_tf(v.x), round_tf(v.y),
                             round_tf(v.z), round_tf(v.w));
    }
}

// ---------------------------------------------------------------------------
// Block reductions
// ---------------------------------------------------------------------------
__device__ __forceinline__ float block_sum(float v, float* sh) {
    int lane = threadIdx.x & 31, w = threadIdx.x >> 5, nw = blockDim.x >> 5;
    #pragma unroll
    for (int o = 16; o; o >>= 1) v += __shfl_xor_sync(0xffffffffu, v, o);
    if (lane == 0) sh[w] = v;
    __syncthreads();
    if (w == 0) {
        v = (lane < nw) ? sh[lane] : 0.0f;
        #pragma unroll
        for (int o = 16; o; o >>= 1) v += __shfl_xor_sync(0xffffffffu, v, o);
        if (lane == 0) sh[0] = v;
    }
    __syncthreads();
    float r = sh[0];
    __syncthreads();
    return r;
}

// ---------------------------------------------------------------------------
// Embedding + sinusoidal PE
// ---------------------------------------------------------------------------
__global__ void embed_kernel(const int* __restrict__ idx,
                             const float* __restrict__ emb,
                             float* __restrict__ x) {
    int row = blockIdx.x;
    int t   = row % Tq;
    int tok = idx[row];
    const float* er = emb + (size_t)tok * Dq;
    const float neg_log = -logf(10000.0f) / (float)Dq;
    for (int d = threadIdx.x; d < Dq; d += blockDim.x) {
        int i2 = d & ~1;
        float freq = expf(neg_log * (float)i2);
        float ang  = (float)t * freq;
        float pe   = (d & 1) ? cosf(ang) : sinf(ang);
        x[(size_t)row * Dq + d] = er[d] + pe;
    }
}

// ---------------------------------------------------------------------------
// LayerNorm; output rounded to tf32 (feeds GEMM A only)
// ---------------------------------------------------------------------------
__global__ void ln_kernel(const float* __restrict__ x,
                          const float* __restrict__ sc,
                          const float* __restrict__ bi,
                          float* __restrict__ out) {
    __shared__ float sh[32];
    int row = blockIdx.x;
    const float* xr = x + (size_t)row * Dq;
    float v[4];
    float lsum = 0.0f;
    #pragma unroll
    for (int i = 0; i < 4; i++) {
        v[i] = xr[threadIdx.x + i * 256];
        lsum += v[i];
    }
    float mean = block_sum(lsum, sh) * (1.0f / (float)Dq);
    float lsq = 0.0f;
    #pragma unroll
    for (int i = 0; i < 4; i++) {
        float d = v[i] - mean;
        lsq += d * d;
    }
    float var = block_sum(lsq, sh) * (1.0f / (float)Dq);
    float inv = rsqrtf(var + 1e-5f);
    #pragma unroll
    for (int i = 0; i < 4; i++) {
        int d = threadIdx.x + i * 256;
        out[(size_t)row * Dq + d] = round_tf((v[i] - mean) * inv * sc[d] + bi[d]);
    }
}

// ---------------------------------------------------------------------------
// TF32 tensor-core GEMM, cp.async double-buffer, 4 warps, warp tile 64x64.
// (unchanged from R5 — proven)
// ---------------------------------------------------------------------------
__device__ __forceinline__ void mma_tf32(float c[4],
                                         unsigned a0, unsigned a1, unsigned a2, unsigned a3,
                                         unsigned b0, unsigned b1) {
    asm volatile(
        "mma.sync.aligned.m16n8k8.row.col.f32.tf32.tf32.f32 "
        "{%0,%1,%2,%3}, {%4,%5,%6,%7}, {%8,%9}, {%0,%1,%2,%3};"
        : "+f"(c[0]), "+f"(c[1]), "+f"(c[2]), "+f"(c[3])
        : "r"(a0), "r"(a1), "r"(a2), "r"(a3), "r"(b0), "r"(b1));
}

#define CP16(dst, src) \
    asm volatile("cp.async.cg.shared.global [%0], [%1], 16;\n" :: "r"(dst), "l"(src))

template <int EPI>
__global__ __launch_bounds__(128)
void tgemm_kernel(const float* __restrict__ A, const float* __restrict__ B,
                  const float* __restrict__ bias, float* __restrict__ C,
                  int M, int N, int K) {
    constexpr int BM = 128, BN = 128, BK = 32;
    constexpr int ASZ = BM * BK;
    constexpr int BSZ = BK * BN;
    extern __shared__ float smf[];
    float* Abuf = smf;
    float* Bbuf = smf + 2 * ASZ;

    int tid  = threadIdx.x;
    int lane = tid & 31;
    int warp = tid >> 5;
    int g    = lane >> 2;
    int tig  = lane & 3;
    int wm   = warp & 1;
    int wn   = warp >> 1;
    int rm   = wm * 64;
    int cn   = wn * 64;
    unsigned xora = (unsigned)(g << 2);
    unsigned xorb = (unsigned)(tig << 3);

    const float* Ab = A + (size_t)(blockIdx.y * BM) * K;
    const float* Bb = B + (size_t)(blockIdx.x) * BN;

    float acc[4][8][4];
    #pragma unroll
    for (int mi = 0; mi < 4; mi++)
        #pragma unroll
        for (int ni = 0; ni < 8; ni++)
            #pragma unroll
            for (int c = 0; c < 4; c++) acc[mi][ni][c] = 0.0f;

    int a_m   = tid >> 3;
    int a_k4  = (tid & 7) << 2;
    int b_k   = tid >> 5;
    int b_n4  = (tid & 31) << 2;
    unsigned xsta = (unsigned)((a_m & 7) << 2);
    unsigned xstb = (unsigned)((b_k & 3) << 3);

    unsigned sA0 = (unsigned)__cvta_generic_to_shared(Abuf);
    unsigned sB0 = (unsigned)__cvta_generic_to_shared(Bbuf);

    auto issue = [&](int kt, int p) {
        unsigned sa = sA0 + (unsigned)(p * ASZ) * 4u;
        unsigned sb = sB0 + (unsigned)(p * BSZ) * 4u;
        #pragma unroll
        for (int i = 0; i < 8; i++) {
            int m = i * 16 + a_m;
            const float* src = Ab + (size_t)m * K + kt + a_k4;
            unsigned dst = sa + (unsigned)(m * 32 + ((unsigned)a_k4 ^ xsta)) * 4u;
            CP16(dst, src);
        }
        #pragma unroll
        for (int i = 0; i < 8; i++) {
            int k = i * 4 + b_k;
            const float* src = Bb + (size_t)(kt + k) * N + b_n4;
            unsigned dst = sb + (unsigned)(k * 128 + ((unsigned)b_n4 ^ xstb)) * 4u;
            CP16(dst, src);
        }
        asm volatile("cp.async.commit_group;\n");
    };

    issue(0, 0);

    int ntiles = K / BK;
    for (int t = 0; t < ntiles; t++) {
        int p = t & 1;
        asm volatile("cp.async.wait_group 0;\n");
        __syncthreads();
        if (t + 1 < ntiles) issue((t + 1) * BK, p ^ 1);

        const float* Ap = Abuf + p * ASZ;
        const float* Bp = Bbuf + p * BSZ;
        #pragma unroll
        for (int ks = 0; ks < 4; ks++) {
            int k0 = ks * 8;
            unsigned af[4][4], bf[8][2];
            unsigned ka0 = (unsigned)(k0 + tig)     ^ xora;
            unsigned ka1 = (unsigned)(k0 + tig + 4) ^ xora;
            #pragma unroll
            for (int mi = 0; mi < 4; mi++) {
                int m1 = rm + mi * 16 + g;
                int m2 = m1 + 8;
                af[mi][0] = __float_as_uint(Ap[m1 * 32 + ka0]);
                af[mi][1] = __float_as_uint(Ap[m2 * 32 + ka0]);
                af[mi][2] = __float_as_uint(Ap[m1 * 32 + ka1]);
                af[mi][3] = __float_as_uint(Ap[m2 * 32 + ka1]);
            }
            #pragma unroll
            for (int ni = 0; ni < 8; ni++) {
                unsigned nb = (unsigned)(cn + ni * 8 + g) ^ xorb;
                bf[ni][0] = __float_as_uint(Bp[(k0 + tig)     * 128 + nb]);
                bf[ni][1] = __float_as_uint(Bp[(k0 + tig + 4) * 128 + nb]);
            }
            #pragma unroll
            for (int mi = 0; mi < 4; mi++)
                #pragma unroll
                for (int ni = 0; ni < 8; ni++)
                    mma_tf32(acc[mi][ni],
                             af[mi][0], af[mi][1], af[mi][2], af[mi][3],
                             bf[ni][0], bf[ni][1]);
        }
        __syncthreads();
    }

    #pragma unroll
    for (int ni = 0; ni < 8; ni++) {
        int gc = blockIdx.x * BN + cn + ni * 8 + 2 * tig;
        float bv0 = bias ? bias[gc]     : 0.0f;
        float bv1 = bias ? bias[gc + 1] : 0.0f;
        #pragma unroll
        for (int mi = 0; mi < 4; mi++) {
            int gr1 = blockIdx.y * BM + rm + mi * 16 + g;
            int gr2 = gr1 + 8;
            float v00 = acc[mi][ni][0] + bv0;
            float v01 = acc[mi][ni][1] + bv1;
            float v10 = acc[mi][ni][2] + bv0;
            float v11 = acc[mi][ni][3] + bv1;
            float* p1 = C + (size_t)gr1 * N + gc;
            float* p2 = C + (size_t)gr2 * N + gc;
            if (EPI == 0) {
                *(float2*)p1 = make_float2(v00, v01);
                *(float2*)p2 = make_float2(v10, v11);
            } else if (EPI == 1) {
                float2 o1 = *(const float2*)p1;
                float2 o2 = *(const float2*)p2;
                *(float2*)p1 = make_float2(o1.x + v00, o1.y + v01);
                *(float2*)p2 = make_float2(o2.x + v10, o2.y + v11);
            } else {
                const float is2 = 0.70710678118654752f;
                *(float2*)p1 = make_float2(
                    round_tf(0.5f * v00 * (1.0f + erff(v00 * is2))),
                    round_tf(0.5f * v01 * (1.0f + erff(v01 * is2))));
                *(float2*)p2 = make_float2(
                    round_tf(0.5f * v10 * (1.0f + erff(v10 * is2))),
                    round_tf(0.5f * v11 * (1.0f + erff(v11 * is2))));
            }
        }
    }
}

// ---------------------------------------------------------------------------
// Tensor-core flash attention. One CTA per (64-query tile, head, batch).
// 4 warps (128 thr); warp w owns query rows w*16..w*16+15.
// S = Q K^T and O += P V via m16n8k8 tf32 MMA.
// Smem strides: Q/K/P = 68 (bank 4g+tig unique), V = 72 (bank 8*tig+g unique).
// ---------------------------------------------------------------------------
#define QPAD 68
#define VPAD 72

__global__ __launch_bounds__(128)
void attn3_kernel(const float* __restrict__ qkv, float* __restrict__ y) {
    extern __shared__ float sm[];
    float* Qs = sm;                       // [64][QPAD]
    float* Ks = Qs + 64 * QPAD;           // [64][QPAD]
    float* Vs = Ks + 64 * QPAD;           // [64][VPAD]
    float* Ps = Vs + 64 * VPAD;           // [64][QPAD]

    int qb = blockIdx.x, h = blockIdx.y, b = blockIdx.z;
    int tid = threadIdx.x;
    int lane = tid & 31, w = tid >> 5;
    int g = lane >> 2, tig = lane & 3;

    const size_t rs = 3 * Dq;
    const float* qbase = qkv + ((size_t)(b * Tq + qb * 64)) * rs + h * HDq;

    // stage Q: 64x64, scaled by 1/8, tf32-rounded
    #pragma unroll
    for (int i = 0; i < 8; i++) {
        int f = tid + i * 128;
        int r = f >> 4, c4 = (f & 15) * 4;
        float4 v = *(const float4*)(qbase + (size_t)r * rs + c4);
        float* dst = Qs + r * QPAD + c4;
        dst[0] = round_tf(v.x * 0.125f);
        dst[1] = round_tf(v.y * 0.125f);
        dst[2] = round_tf(v.z * 0.125f);
        dst[3] = round_tf(v.w * 0.125f);
    }

    float oacc[8][4];
    #pragma unroll
    for (int ni = 0; ni < 8; ni++)
        #pragma unroll
        for (int c = 0; c < 4; c++) oacc[ni][c] = 0.0f;
    float mrow0 = -CUDART_INF_F, mrow1 = -CUDART_INF_F;
    float lrow0 = 0.0f, lrow1 = 0.0f;

    int rloc0 = w * 16 + g;        // this thread's two rows (local)
    int rloc1 = rloc0 + 8;

    for (int kt = 0; kt <= qb; kt++) {
        __syncthreads();
        const float* kbase = qkv + ((size_t)(b * Tq + kt * 64)) * rs + Dq + h * HDq;
        const float* vbase = kbase + Dq;
        #pragma unroll
        for (int i = 0; i < 8; i++) {
            int f = tid + i * 128;
            int r = f >> 4, c4 = (f & 15) * 4;
            float4 kv = *(const float4*)(kbase + (size_t)r * rs + c4);
            float4 vv = *(const float4*)(vbase + (size_t)r * rs + c4);
            float* kd = Ks + r * QPAD + c4;
            kd[0] = round_tf(kv.x); kd[1] = round_tf(kv.y);
            kd[2] = round_tf(kv.z); kd[3] = round_tf(kv.w);
            float* vd = Vs + r * VPAD + c4;
            vd[0] = round_tf(vv.x); vd[1] = round_tf(vv.y);
            vd[2] = round_tf(vv.z); vd[3] = round_tf(vv.w);
        }
        __syncthreads();

        // ---- S = Q K^T ----
        float sacc[8][4];
        #pragma unroll
        for (int ni = 0; ni < 8; ni++)
            #pragma unroll
            for (int c = 0; c < 4; c++) sacc[ni][c] = 0.0f;
        #pragma unroll
        for (int ks = 0; ks < 8; ks++) {
            int k0 = ks * 8;
            unsigned a0 = __float_as_uint(Qs[rloc0 * QPAD + k0 + tig]);
            unsigned a1 = __float_as_uint(Qs[rloc1 * QPAD + k0 + tig]);
            unsigned a2 = __float_as_uint(Qs[rloc0 * QPAD + k0 + tig + 4]);
            unsigned a3 = __float_as_uint(Qs[rloc1 * QPAD + k0 + tig + 4]);
            #pragma unroll
            for (int ni = 0; ni < 8; ni++) {
                unsigned b0 = __float_as_uint(Ks[(ni * 8 + g) * QPAD + k0 + tig]);
                unsigned b1 = __float_as_uint(Ks[(ni * 8 + g) * QPAD + k0 + tig + 4]);
                mma_tf32(sacc[ni], a0, a1, a2, a3, b0, b1);
            }
        }

        // ---- causal mask on diagonal tile ----
        if (kt == qb) {
            #pragma unroll
            for (int ni = 0; ni < 8; ni++) {
                int c0 = ni * 8 + 2 * tig, c1 = c0 + 1;
                if (c0 > rloc0) sacc[ni][0] = -CUDART_INF_F;
                if (c1 > rloc0) sacc[ni][1] = -CUDART_INF_F;
                if (c0 > rloc1) sacc[ni][2] = -CUDART_INF_F;
                if (c1 > rloc1) sacc[ni][3] = -CUDART_INF_F;
            }
        }

        // ---- online softmax (rows rloc0, rloc1; 4 lanes per row via tig) ----
        float mx0 = -CUDART_INF_F, mx1 = -CUDART_INF_F;
        #pragma unroll
        for (int ni = 0; ni < 8; ni++) {
            mx0 = fmaxf(mx0, fmaxf(sacc[ni][0], sacc[ni][1]));
            mx1 = fmaxf(mx1, fmaxf(sacc[ni][2], sacc[ni][3]));
        }
        mx0 = fmaxf(mx0, __shfl_xor_sync(0xffffffffu, mx0, 1));
        mx0 = fmaxf(mx0, __shfl_xor_sync(0xffffffffu, mx0, 2));
        mx1 = fmaxf(mx1, __shfl_xor_sync(0xffffffffu, mx1, 1));
        mx1 = fmaxf(mx1, __shfl_xor_sync(0xffffffffu, mx1, 2));

        float mn0 = fmaxf(mrow0, mx0);
        float mn1 = fmaxf(mrow1, mx1);
        float corr0 = __expf(mrow0 - mn0);
        float corr1 = __expf(mrow1 - mn1);

        float rs0 = 0.0f, rs1 = 0.0f;
        #pragma unroll
        for (int ni = 0; ni < 8; ni++) {
            float p00 = round_tf(__expf(sacc[ni][0] - mn0));
            float p01 = round_tf(__expf(sacc[ni][1] - mn0));
            float p10 = round_tf(__expf(sacc[ni][2] - mn1));
            float p11 = round_tf(__expf(sacc[ni][3] - mn1));
            rs0 += p00 + p01;
            rs1 += p10 + p11;
            int c0 = ni * 8 + 2 * tig;
            *(float2*)&Ps[rloc0 * QPAD + c0] = make_float2(p00, p01);
            *(float2*)&Ps[rloc1 * QPAD + c0] = make_float2(p10, p11);
        }
        rs0 += __shfl_xor_sync(0xffffffffu, rs0, 1);
        rs0 += __shfl_xor_sync(0xffffffffu, rs0, 2);
        rs1 += __shfl_xor_sync(0xffffffffu, rs1, 1);
        rs1 += __shfl_xor_sync(0xffffffffu, rs1, 2);

        lrow0 = lrow0 * corr0 + rs0;
        lrow1 = lrow1 * corr1 + rs1;
        mrow0 = mn0; mrow1 = mn1;

        #pragma unroll
        for (int ni = 0; ni < 8; ni++) {
            oacc[ni][0] *= corr0; oacc[ni][1] *= corr0;
            oacc[ni][2] *= corr1; oacc[ni][3] *= corr1;
        }
        __syncwarp();

        // ---- O += P V ----
        #pragma unroll
        for (int ks = 0; ks < 8; ks++) {
            int k0 = ks * 8;
            unsigned a0 = __float_as_uint(Ps[rloc0 * QPAD + k0 + tig]);
            unsigned a1 = __float_as_uint(Ps[rloc1 * QPAD + k0 + tig]);
            unsigned a2 = __float_as_uint(Ps[rloc0 * QPAD + k0 + tig + 4]);
            unsigned a3 = __float_as_uint(Ps[rloc1 * QPAD + k0 + tig + 4]);
            #pragma unroll
            for (int ni = 0; ni < 8; ni++) {
                unsigned b0 = __float_as_uint(Vs[(k0 + tig)     * VPAD + ni * 8 + g]);
                unsigned b1 = __float_as_uint(Vs[(k0 + tig + 4) * VPAD + ni * 8 + g]);
                mma_tf32(oacc[ni], a0, a1, a2, a3, b0, b1);
            }
        }
        __syncwarp();
    }

    // ---- epilogue: normalize and store (tf32-rounded; feeds out-proj A) ----
    float inv0 = 1.0f / lrow0;
    float inv1 = 1.0f / lrow1;
    size_t row0 = (size_t)(b * Tq + qb * 64 + rloc0);
    size_t row1 = row0 + 8;
    #pragma unroll
    for (int ni = 0; ni < 8; ni++) {
        int col = h * HDq + ni * 8 + 2 * tig;
        *(float2*)&y[row0 * Dq + col] = make_float2(
            round_tf(oacc[ni][0] * inv0), round_tf(oacc[ni][1] * inv0));
        *(float2*)&y[row1 * Dq + col] = make_float2(
            round_tf(oacc[ni][2] * inv1), round_tf(oacc[ni][3] * inv1));
    }
}

// ---------------------------------------------------------------------------
// Launch
// ---------------------------------------------------------------------------
extern "C" void kernel_launch(void* const* d_in, const int* in_sizes, int n_in,
                              void* d_out, int out_size) {
    const int*   idx     = (const int*)  d_in[0];
    const float* tok_emb = (const float*)d_in[1];
    const float* ln1_s   = (const float*)d_in[2];
    const float* ln1_b   = (const float*)d_in[3];
    const float* qkv_w   = (const float*)d_in[4];
    const float* qkv_b   = (const float*)d_in[5];
    const float* out_w   = (const float*)d_in[6];
    const float* out_b   = (const float*)d_in[7];
    const float* ln2_s   = (const float*)d_in[8];
    const float* ln2_b   = (const float*)d_in[9];
    const float* mlp_w1  = (const float*)d_in[10];
    const float* mlp_b1  = (const float*)d_in[11];
    const float* mlp_w2  = (const float*)d_in[12];
    const float* mlp_b2  = (const float*)d_in[13];
    const float* lnf_s   = (const float*)d_in[14];
    const float* lnf_b   = (const float*)d_in[15];
    const float* head_w  = (const float*)d_in[16];
    float* logits = (float*)d_out;

    float *x, *ln, *qkv, *y, *ff;
    float *wqkv, *wout, *wm1, *wm2, *whd;
    cudaGetSymbolAddress((void**)&x,    g_x);
    cudaGetSymbolAddress((void**)&ln,   g_ln);
    cudaGetSymbolAddress((void**)&qkv,  g_qkv);
    cudaGetSymbolAddress((void**)&y,    g_y);
    cudaGetSymbolAddress((void**)&ff,   g_ff);
    cudaGetSymbolAddress((void**)&wqkv, g_wqkv);
    cudaGetSymbolAddress((void**)&wout, g_wout);
    cudaGetSymbolAddress((void**)&wm1,  g_wm1);
    cudaGetSymbolAddress((void**)&wm2,  g_wm2);
    cudaGetSymbolAddress((void**)&whd,  g_whd);

    const int gemm_smem = 2 * (128 * 32 + 32 * 128) * (int)sizeof(float);  // 64 KB
    cudaFuncSetAttribute(tgemm_kernel<0>,
                         cudaFuncAttributeMaxDynamicSharedMemorySize, gemm_smem);
    cudaFuncSetAttribute(tgemm_kernel<1>,
                         cudaFuncAttributeMaxDynamicSharedMemorySize, gemm_smem);
    cudaFuncSetAttribute(tgemm_kernel<2>,
                         cudaFuncAttributeMaxDynamicSharedMemorySize, gemm_smem);
    const int attn_smem = (3 * 64 * QPAD + 64 * VPAD) * (int)sizeof(float);  // ~70.7 KB
    cudaFuncSetAttribute(attn3_kernel,
                         cudaFuncAttributeMaxDynamicSharedMemorySize, attn_smem);

    // round weights to tf32 once (vectorized)
    auto rnd = [](const float* src, float* dst, int n) {
        int n4 = n / 4;
        round4_kernel<<<(n4 + 255) / 256, 256>>>((const float4*)src, (float4*)dst, n4);
    };
    rnd(qkv_w,  wqkv, Lq * Dq * 3 * Dq);
    rnd(out_w,  wout, Lq * Dq * Dq);
    rnd(mlp_w1, wm1,  Lq * Dq * FFq);
    rnd(mlp_w2, wm2,  Lq * FFq * Dq);
    rnd(head_w, whd,  Dq * Vq);

    embed_kernel<<<Rq, 256>>>(idx, tok_emb, x);

    for (int l = 0; l < Lq; l++) {
        ln_kernel<<<Rq, 256>>>(x, ln1_s + (size_t)l * Dq, ln1_b + (size_t)l * Dq, ln);
        tgemm_kernel<0><<<dim3(3 * Dq / 128, Rq / 128), 128, gemm_smem>>>(
            ln, wqkv + (size_t)l * Dq * 3 * Dq, qkv_b + (size_t)l * 3 * Dq,
            qkv, Rq, 3 * Dq, Dq);
        attn3_kernel<<<dim3(Tq / 64, Hq, Bq), 128, attn_smem>>>(qkv, y);
        tgemm_kernel<1><<<dim3(Dq / 128, Rq / 128), 128, gemm_smem>>>(
            y, wout + (size_t)l * Dq * Dq, out_b + (size_t)l * Dq,
            x, Rq, Dq, Dq);
        ln_kernel<<<Rq, 256>>>(x, ln2_s + (size_t)l * Dq, ln2_b + (size_t)l * Dq, ln);
        tgemm_kernel<2><<<dim3(FFq / 128, Rq / 128), 128, gemm_smem>>>(
            ln, wm1 + (size_t)l * Dq * FFq, mlp_b1 + (size_t)l * FFq,
            ff, Rq, FFq, Dq);
        tgemm_kernel<1><<<dim3(Dq / 128, Rq / 128), 128, gemm_smem>>>(
            ff, wm2 + (size_t)l * FFq * Dq, mlp_b2 + (size_t)l * Dq,
            x, Rq, Dq, FFq);
    }

    ln_kernel<<<Rq, 256>>>(x, lnf_s, lnf_b, ln);
    tgemm_kernel<0><<<dim3(Vq / 128, Rq / 128), 128, gemm_smem>>>(
        ln, whd, (const float*)nullptr, logits, Rq, Vq, Dq);
}